// round 1
// baseline (speedup 1.0000x reference)
#include <cuda_runtime.h>

// Problem constants
constexpr int DS = 128;        // scalar feature dim
constexpr int DV = 64;         // vector feature dim
constexpr int NN = 20000;      // nodes
constexpr int EE = 640000;     // edges
constexpr int TE = 128;        // tile (edges or nodes) per block
constexpr int NTHREADS = 256;
constexpr int XPITCH = 132;    // padded smem row pitch (floats)

// Scratch (no allocation allowed -> device globals)
__device__ float g_P[(size_t)NN * DS];        // s @ W1a + b1
__device__ float g_Q[(size_t)NN * DS];        // s @ W1b
__device__ float g_sout[(size_t)NN * DS];     // scatter accumulator (scalar)
__device__ float g_vout[(size_t)NN * DV * 3]; // scatter accumulator (vector)

__device__ __forceinline__ float silu_f(float x) {
    return x / (1.0f + __expf(-x));
}

extern __shared__ float smem_f[];

// ---------------------------------------------------------------------------
// Shared 128x128x128 GEMM tile helper.
// Xsrc: [TE][XPITCH] smem tile ([row][k] layout).
// Wg:   global weights [128][128] row-major (k-major).
// Wb:   smem staging buffer 16*128 floats.
// Thread map: c = tid&15 (8 cols each), r = tid>>4 (8 rows each).
// ---------------------------------------------------------------------------
__device__ __forceinline__ void gemm_128(const float* __restrict__ Xsrc,
                                         const float* __restrict__ Wg,
                                         float* Wb, int c, int r,
                                         float acc[8][8]) {
    for (int kc = 0; kc < DS; kc += 16) {
        __syncthreads();  // Wb free to overwrite; Xsrc writes (if any) visible
        for (int idx = threadIdx.x; idx < 16 * 32; idx += NTHREADS) {
            int kk = idx >> 5, j4 = idx & 31;
            *(float4*)&Wb[kk * DS + j4 * 4] =
                __ldg((const float4*)(Wg + (size_t)(kc + kk) * DS) + j4);
        }
        __syncthreads();
#pragma unroll
        for (int kk = 0; kk < 16; ++kk) {
            float xv[8];
#pragma unroll
            for (int i = 0; i < 8; ++i)
                xv[i] = Xsrc[(r * 8 + i) * XPITCH + kc + kk];
            float4 w0 = *(const float4*)&Wb[kk * DS + c * 8];
            float4 w1 = *(const float4*)&Wb[kk * DS + c * 8 + 4];
            float wv[8] = {w0.x, w0.y, w0.z, w0.w, w1.x, w1.y, w1.z, w1.w};
#pragma unroll
            for (int i = 0; i < 8; ++i)
#pragma unroll
                for (int j = 0; j < 8; ++j)
                    acc[i][j] = fmaf(xv[i], wv[j], acc[i][j]);
        }
    }
}

// ---------------------------------------------------------------------------
// Zero the scatter accumulators.
// ---------------------------------------------------------------------------
__global__ void zero_kernel() {
    int i = blockIdx.x * blockDim.x + threadIdx.x;
    float4 z = make_float4(0.f, 0.f, 0.f, 0.f);
    constexpr int ns4 = NN * DS / 4;       // 640000
    constexpr int nv4 = NN * DV * 3 / 4;   // 960000
    if (i < ns4) ((float4*)g_sout)[i] = z;
    if (i < nv4) ((float4*)g_vout)[i] = z;
}

// ---------------------------------------------------------------------------
// Node pre-GEMM: P = s @ W1[0:128] + b1 ; Q = s @ W1[128:256]
// blockIdx.y: 0 -> P, 1 -> Q
// ---------------------------------------------------------------------------
__global__ __launch_bounds__(NTHREADS, 1)
void node_pre_kernel(const float* __restrict__ s,
                     const float* __restrict__ W1,
                     const float* __restrict__ b1) {
    float* Xs = smem_f;                 // TE x XPITCH
    float* Wb = Xs + TE * XPITCH;       // 16 x 128
    int tid = threadIdx.x;
    int n0 = blockIdx.x * TE;
    int half = blockIdx.y;
    const float* W = W1 + (size_t)half * DS * DS;

    for (int idx = tid; idx < TE * 32; idx += NTHREADS) {
        int e = idx >> 5, k4 = idx & 31;
        int n = n0 + e;
        float4 v = make_float4(0.f, 0.f, 0.f, 0.f);
        if (n < NN) v = ((const float4*)(s + (size_t)n * DS))[k4];
        *(float4*)&Xs[e * XPITCH + k4 * 4] = v;
    }

    int c = tid & 15, r = tid >> 4;
    float acc[8][8];
#pragma unroll
    for (int i = 0; i < 8; ++i)
#pragma unroll
        for (int j = 0; j < 8; ++j) acc[i][j] = 0.f;

    gemm_128(Xs, W, Wb, c, r, acc);

    float bb[8];
    if (half == 0) {
#pragma unroll
        for (int j = 0; j < 8; ++j) bb[j] = __ldg(b1 + c * 8 + j);
    } else {
#pragma unroll
        for (int j = 0; j < 8; ++j) bb[j] = 0.f;
    }
    float* out = half ? g_Q : g_P;
#pragma unroll
    for (int i = 0; i < 8; ++i) {
        int n = n0 + r * 8 + i;
        if (n >= NN) continue;
        float4 o0 = make_float4(acc[i][0] + bb[0], acc[i][1] + bb[1],
                                acc[i][2] + bb[2], acc[i][3] + bb[3]);
        float4 o1 = make_float4(acc[i][4] + bb[4], acc[i][5] + bb[5],
                                acc[i][6] + bb[6], acc[i][7] + bb[7]);
        float4* dst = (float4*)(out + (size_t)n * DS + c * 8);
        dst[0] = o0;
        dst[1] = o1;
    }
}

// ---------------------------------------------------------------------------
// Edge kernel: per 128-edge tile
//   h1 = silu(EA@W1c + P[row] + Q[col])        (b1 folded into P)
//   msg = h1@W2 + b2        -> atomicAdd into g_sout[row]
//   g  = silu(msg)@Wv + bv  -> atomicAdd g*unit into g_vout[row]
// ---------------------------------------------------------------------------
__global__ __launch_bounds__(NTHREADS, 1)
void edge_kernel(const int* __restrict__ ei,
                 const float* __restrict__ ea,
                 const float* __restrict__ evu,
                 const float* __restrict__ W1,
                 const float* __restrict__ W2,
                 const float* __restrict__ b2,
                 const float* __restrict__ Wv,
                 const float* __restrict__ bv) {
    float* Xs = smem_f;                      // TE x XPITCH
    float* Hs = Xs + TE * XPITCH;            // TE x XPITCH
    float* Wb = Hs + TE * XPITCH;            // 16 x 128
    int* rows = (int*)(Wb + 16 * DS);        // TE
    int* cols = rows + TE;                   // TE
    float* uv = (float*)(cols + TE);         // TE x 3

    int tid = threadIdx.x;
    int e0 = blockIdx.x * TE;

    if (tid < TE) {
        rows[tid] = ei[e0 + tid];
        cols[tid] = ei[EE + e0 + tid];
    }
    for (int idx = tid; idx < TE * 3; idx += NTHREADS)
        uv[idx] = evu[(size_t)e0 * 3 + idx];
    // X tile = edge_attr rows (coalesced)
    for (int idx = tid; idx < TE * 32; idx += NTHREADS) {
        int e = idx >> 5, k4 = idx & 31;
        *(float4*)&Xs[e * XPITCH + k4 * 4] =
            ((const float4*)(ea + (size_t)(e0 + e) * DS))[k4];
    }
    __syncthreads();  // rows/cols ready for gather

    // Hs <- P[row] + Q[col]   (includes b1)
    for (int idx = tid; idx < TE * 32; idx += NTHREADS) {
        int e = idx >> 5, j4 = idx & 31;
        float4 p = ((const float4*)(g_P + (size_t)rows[e] * DS))[j4];
        float4 q = ((const float4*)(g_Q + (size_t)cols[e] * DS))[j4];
        p.x += q.x; p.y += q.y; p.z += q.z; p.w += q.w;
        *(float4*)&Hs[e * XPITCH + j4 * 4] = p;
    }

    int c = tid & 15, r = tid >> 4;
    float acc[8][8];
#pragma unroll
    for (int i = 0; i < 8; ++i)
#pragma unroll
        for (int j = 0; j < 8; ++j) acc[i][j] = 0.f;

    // GEMM1: EA @ W1c  (W1c = rows 256..383 of W1)
    gemm_128(Xs, W1 + (size_t)2 * DS * DS, Wb, c, r, acc);

    // h1 = silu(acc + PQ); stash to registers, then overwrite Xs
    float h1[8][8];
#pragma unroll
    for (int i = 0; i < 8; ++i)
#pragma unroll
        for (int j = 0; j < 8; ++j)
            h1[i][j] = silu_f(acc[i][j] + Hs[(r * 8 + i) * XPITCH + c * 8 + j]);
    __syncthreads();  // everyone done reading Xs (GEMM1)
#pragma unroll
    for (int i = 0; i < 8; ++i) {
        *(float4*)&Xs[(r * 8 + i) * XPITCH + c * 8] =
            make_float4(h1[i][0], h1[i][1], h1[i][2], h1[i][3]);
        *(float4*)&Xs[(r * 8 + i) * XPITCH + c * 8 + 4] =
            make_float4(h1[i][4], h1[i][5], h1[i][6], h1[i][7]);
    }
#pragma unroll
    for (int i = 0; i < 8; ++i)
#pragma unroll
        for (int j = 0; j < 8; ++j) acc[i][j] = 0.f;

    // GEMM2: h1 @ W2  (gemm's internal sync publishes Xs writes)
    gemm_128(Xs, W2, Wb, c, r, acc);

    float bb[8];
#pragma unroll
    for (int j = 0; j < 8; ++j) bb[j] = __ldg(b2 + c * 8 + j);
    // msg = acc + b2 ; scatter ; h2 = silu(msg) -> Hs
#pragma unroll
    for (int i = 0; i < 8; ++i) {
        int rw = rows[r * 8 + i];
        float* sdst = g_sout + (size_t)rw * DS + c * 8;
#pragma unroll
        for (int j = 0; j < 8; ++j) {
            float m = acc[i][j] + bb[j];
            atomicAdd(&sdst[j], m);
            Hs[(r * 8 + i) * XPITCH + c * 8 + j] = silu_f(m);
        }
    }

    // GEMM3: h2 @ Wv  (128x64), thread map c3 = tid&7 (8 cols), r3 = tid>>3 (4 rows)
    int c3 = tid & 7, r3 = tid >> 3;
    float a3[4][8];
#pragma unroll
    for (int i = 0; i < 4; ++i)
#pragma unroll
        for (int j = 0; j < 8; ++j) a3[i][j] = 0.f;

    for (int kc = 0; kc < DS; kc += 16) {
        __syncthreads();  // Hs writes visible on first iter; Wb free
        {
            int kk = tid >> 4, j4 = tid & 15;  // 256 threads -> 16x16 float4
            *(float4*)&Wb[kk * DV + j4 * 4] =
                __ldg((const float4*)(Wv + (size_t)(kc + kk) * DV) + j4);
        }
        __syncthreads();
#pragma unroll
        for (int kk = 0; kk < 16; ++kk) {
            float xv[4];
#pragma unroll
            for (int i = 0; i < 4; ++i)
                xv[i] = Hs[(r3 * 4 + i) * XPITCH + kc + kk];
            float4 w0 = *(const float4*)&Wb[kk * DV + c3 * 8];
            float4 w1 = *(const float4*)&Wb[kk * DV + c3 * 8 + 4];
            float wv[8] = {w0.x, w0.y, w0.z, w0.w, w1.x, w1.y, w1.z, w1.w};
#pragma unroll
            for (int i = 0; i < 4; ++i)
#pragma unroll
                for (int j = 0; j < 8; ++j)
                    a3[i][j] = fmaf(xv[i], wv[j], a3[i][j]);
        }
    }

    float bb3[8];
#pragma unroll
    for (int j = 0; j < 8; ++j) bb3[j] = __ldg(bv + c3 * 8 + j);
#pragma unroll
    for (int i = 0; i < 4; ++i) {
        int e = r3 * 4 + i;
        int rw = rows[e];
        float ux = uv[e * 3 + 0], uy = uv[e * 3 + 1], uz = uv[e * 3 + 2];
        float* vdst = g_vout + (size_t)rw * (DV * 3) + c3 * 8 * 3;
#pragma unroll
        for (int j = 0; j < 8; ++j) {
            float g = a3[i][j] + bb3[j];
            atomicAdd(&vdst[j * 3 + 0], g * ux);
            atomicAdd(&vdst[j * 3 + 1], g * uy);
            atomicAdd(&vdst[j * 3 + 2], g * uz);
        }
    }
}

// ---------------------------------------------------------------------------
// Node post: s_mid = s + silu(g_sout)@Ws + bs ; LayerNorm -> out_s
// ---------------------------------------------------------------------------
__global__ __launch_bounds__(NTHREADS, 1)
void node_post_kernel(const float* __restrict__ s,
                      const float* __restrict__ Ws,
                      const float* __restrict__ bs,
                      const float* __restrict__ gamma,
                      const float* __restrict__ beta,
                      float* __restrict__ out_s) {
    float* Xs = smem_f;                   // TE x XPITCH (silu(s_out))
    float* Hs = Xs + TE * XPITCH;         // TE x XPITCH (s_mid)
    float* Wb = Hs + TE * XPITCH;         // 16 x 128
    float* mu = Wb + 16 * DS;             // TE
    float* rs = mu + TE;                  // TE

    int tid = threadIdx.x;
    int n0 = blockIdx.x * TE;

    for (int idx = tid; idx < TE * 32; idx += NTHREADS) {
        int e = idx >> 5, k4 = idx & 31;
        int n = n0 + e;
        float4 v = make_float4(0.f, 0.f, 0.f, 0.f);
        if (n < NN) {
            v = ((const float4*)(g_sout + (size_t)n * DS))[k4];
            v.x = silu_f(v.x); v.y = silu_f(v.y);
            v.z = silu_f(v.z); v.w = silu_f(v.w);
        }
        *(float4*)&Xs[e * XPITCH + k4 * 4] = v;
    }

    int c = tid & 15, r = tid >> 4;
    float acc[8][8];
#pragma unroll
    for (int i = 0; i < 8; ++i)
#pragma unroll
        for (int j = 0; j < 8; ++j) acc[i][j] = 0.f;

    gemm_128(Xs, Ws, Wb, c, r, acc);

    float bb[8];
#pragma unroll
    for (int j = 0; j < 8; ++j) bb[j] = __ldg(bs + c * 8 + j);
#pragma unroll
    for (int i = 0; i < 8; ++i) {
        int n = n0 + r * 8 + i;
        float4 s0 = make_float4(0.f, 0.f, 0.f, 0.f);
        float4 s1 = make_float4(0.f, 0.f, 0.f, 0.f);
        if (n < NN) {
            const float4* sp = (const float4*)(s + (size_t)n * DS + c * 8);
            s0 = sp[0];
            s1 = sp[1];
        }
        Hs[(r * 8 + i) * XPITCH + c * 8 + 0] = s0.x + acc[i][0] + bb[0];
        Hs[(r * 8 + i) * XPITCH + c * 8 + 1] = s0.y + acc[i][1] + bb[1];
        Hs[(r * 8 + i) * XPITCH + c * 8 + 2] = s0.z + acc[i][2] + bb[2];
        Hs[(r * 8 + i) * XPITCH + c * 8 + 3] = s0.w + acc[i][3] + bb[3];
        Hs[(r * 8 + i) * XPITCH + c * 8 + 4] = s1.x + acc[i][4] + bb[4];
        Hs[(r * 8 + i) * XPITCH + c * 8 + 5] = s1.y + acc[i][5] + bb[5];
        Hs[(r * 8 + i) * XPITCH + c * 8 + 6] = s1.z + acc[i][6] + bb[6];
        Hs[(r * 8 + i) * XPITCH + c * 8 + 7] = s1.w + acc[i][7] + bb[7];
    }
    __syncthreads();

    if (tid < TE) {
        float sum = 0.f, sq = 0.f;
#pragma unroll 8
        for (int k = 0; k < DS; ++k) {
            float x = Hs[tid * XPITCH + k];
            sum += x;
            sq += x * x;
        }
        float m = sum * (1.0f / DS);
        float var = sq * (1.0f / DS) - m * m;
        mu[tid] = m;
        rs[tid] = rsqrtf(var + 1e-5f);
    }
    __syncthreads();

    for (int idx = tid; idx < TE * 32; idx += NTHREADS) {
        int e = idx >> 5, j4 = idx & 31;
        int n = n0 + e;
        if (n >= NN) continue;
        float4 x = *(const float4*)&Hs[e * XPITCH + j4 * 4];
        float4 g = __ldg((const float4*)gamma + j4);
        float4 b = __ldg((const float4*)beta + j4);
        float m = mu[e], iv = rs[e];
        float4 o;
        o.x = (x.x - m) * iv * g.x + b.x;
        o.y = (x.y - m) * iv * g.y + b.y;
        o.z = (x.z - m) * iv * g.z + b.z;
        o.w = (x.w - m) * iv * g.w + b.w;
        ((float4*)(out_s + (size_t)n * DS))[j4] = o;
    }
}

// ---------------------------------------------------------------------------
// v_new = v + v_out
// ---------------------------------------------------------------------------
__global__ void vadd_kernel(const float* __restrict__ v, float* __restrict__ out_v) {
    int i = blockIdx.x * blockDim.x + threadIdx.x;
    constexpr int nv4 = NN * DV * 3 / 4;
    if (i < nv4) {
        float4 a = ((const float4*)v)[i];
        float4 b = ((const float4*)g_vout)[i];
        a.x += b.x; a.y += b.y; a.z += b.z; a.w += b.w;
        ((float4*)out_v)[i] = a;
    }
}

// ---------------------------------------------------------------------------
extern "C" void kernel_launch(void* const* d_in, const int* in_sizes, int n_in,
                              void* d_out, int out_size) {
    const float* s     = (const float*)d_in[0];
    const float* v     = (const float*)d_in[1];
    const int*   ei    = (const int*)d_in[2];
    const float* ea    = (const float*)d_in[3];
    const float* evu   = (const float*)d_in[4];
    const float* W1    = (const float*)d_in[5];
    const float* b1    = (const float*)d_in[6];
    const float* W2    = (const float*)d_in[7];
    const float* b2    = (const float*)d_in[8];
    const float* Ws    = (const float*)d_in[9];
    const float* bs    = (const float*)d_in[10];
    const float* Wv    = (const float*)d_in[11];
    const float* bv    = (const float*)d_in[12];
    const float* gamma = (const float*)d_in[13];
    const float* beta  = (const float*)d_in[14];
    float* out = (float*)d_out;

    const int SMEM_PRE  = (TE * XPITCH + 16 * DS) * 4;
    const int SMEM_EDGE = (2 * TE * XPITCH + 16 * DS) * 4 + 2 * TE * 4 + TE * 3 * 4;
    const int SMEM_POST = (2 * TE * XPITCH + 16 * DS) * 4 + 2 * TE * 4;

    cudaFuncSetAttribute(node_pre_kernel,
                         cudaFuncAttributeMaxDynamicSharedMemorySize, SMEM_PRE);
    cudaFuncSetAttribute(edge_kernel,
                         cudaFuncAttributeMaxDynamicSharedMemorySize, SMEM_EDGE);
    cudaFuncSetAttribute(node_post_kernel,
                         cudaFuncAttributeMaxDynamicSharedMemorySize, SMEM_POST);

    zero_kernel<<<(NN * DV * 3 / 4 + 255) / 256, 256>>>();

    dim3 gpre((NN + TE - 1) / TE, 2);
    node_pre_kernel<<<gpre, NTHREADS, SMEM_PRE>>>(s, W1, b1);

    edge_kernel<<<EE / TE, NTHREADS, SMEM_EDGE>>>(ei, ea, evu, W1, W2, b2, Wv, bv);

    node_post_kernel<<<(NN + TE - 1) / TE, NTHREADS, SMEM_POST>>>(s, Ws, bs, gamma,
                                                                  beta, out);

    vadd_kernel<<<(NN * DV * 3 / 4 + 255) / 256, 256>>>(v, out + (size_t)NN * DS);
}

// round 4
// speedup vs baseline: 1.2743x; 1.2743x over previous
#include <cuda_runtime.h>

// Problem constants
constexpr int DS = 128;        // scalar feature dim
constexpr int DV = 64;         // vector feature dim
constexpr int NN = 20000;      // nodes
constexpr int EE = 640000;     // edges
constexpr int TE = 128;        // tile (edges or nodes) per block
constexpr int NTHREADS = 256;
constexpr int XPITCH = 132;    // padded smem row pitch (floats)

using ull = unsigned long long;

// Scratch (no allocation allowed -> device globals)
__device__ float g_P[(size_t)NN * DS];        // s @ W1a + b1
__device__ float g_Q[(size_t)NN * DS];        // s @ W1b
__device__ float g_sout[(size_t)NN * DS];     // scatter accumulator (scalar)
__device__ float g_vout[(size_t)NN * DV * 3]; // scatter accumulator (vector)

__device__ __forceinline__ float silu_f(float x) {
    return x / (1.0f + __expf(-x));
}

// ---- packed f32x2 helpers (sm_100+) --------------------------------------
__device__ __forceinline__ ull splat2(float x) {
    ull r;
    asm("mov.b64 %0, {%1, %1};" : "=l"(r) : "f"(x));
    return r;
}
__device__ __forceinline__ void ffma2(ull& a, ull x, ull w) {
    asm("fma.rn.f32x2 %0, %1, %2, %0;" : "+l"(a) : "l"(x), "l"(w));
}
__device__ __forceinline__ float2 unpack2(ull a) {
    float2 f;
    asm("mov.b64 {%0, %1}, %2;" : "=f"(f.x), "=f"(f.y) : "l"(a));
    return f;
}
// vectorized global reduction
__device__ __forceinline__ void red4(float* p, float a, float b, float c, float d) {
    asm volatile("red.global.add.v4.f32 [%0], {%1,%2,%3,%4};"
                 :: "l"(p), "f"(a), "f"(b), "f"(c), "f"(d) : "memory");
}

extern __shared__ float smem_f[];

// ---------------------------------------------------------------------------
// 128x128x128 GEMM tile helper with packed f32x2 accumulation.
// Xsrc: [TE][XPITCH] smem tile. Wg: [128][128] row-major global.
// Wb: 16x128 smem staging. Thread map: c=tid&15 (4 j-pairs), r=tid>>4 (8 rows).
// ---------------------------------------------------------------------------
__device__ __forceinline__ void gemm_128(const float* __restrict__ Xsrc,
                                         const float* __restrict__ Wg,
                                         float* Wb, int c, int r,
                                         ull (&acc2)[8][4]) {
    for (int kc = 0; kc < DS; kc += 16) {
        __syncthreads();  // Wb free; Xsrc writes (if any) visible
        for (int idx = threadIdx.x; idx < 16 * 32; idx += NTHREADS) {
            int kk = idx >> 5, j4 = idx & 31;
            *(float4*)&Wb[kk * DS + j4 * 4] =
                __ldg((const float4*)(Wg + (size_t)(kc + kk) * DS) + j4);
        }
        __syncthreads();
#pragma unroll
        for (int kk4 = 0; kk4 < 4; ++kk4) {
            float4 xq[8];
#pragma unroll
            for (int i = 0; i < 8; ++i)
                xq[i] = *(const float4*)&Xsrc[(r * 8 + i) * XPITCH + kc + kk4 * 4];
#pragma unroll
            for (int t = 0; t < 4; ++t) {
                int kk = kk4 * 4 + t;
                const ulonglong2* wp = (const ulonglong2*)&Wb[kk * DS + c * 8];
                ulonglong2 wa = wp[0];
                ulonglong2 wb = wp[1];
#pragma unroll
                for (int i = 0; i < 8; ++i) {
                    ull xs = splat2(((const float*)&xq[i])[t]);
                    ffma2(acc2[i][0], xs, wa.x);
                    ffma2(acc2[i][1], xs, wa.y);
                    ffma2(acc2[i][2], xs, wb.x);
                    ffma2(acc2[i][3], xs, wb.y);
                }
            }
        }
    }
}

// ---------------------------------------------------------------------------
// Zero the scatter accumulators.
// ---------------------------------------------------------------------------
__global__ void zero_kernel() {
    int i = blockIdx.x * blockDim.x + threadIdx.x;
    float4 z = make_float4(0.f, 0.f, 0.f, 0.f);
    constexpr int ns4 = NN * DS / 4;       // 640000
    constexpr int nv4 = NN * DV * 3 / 4;   // 960000
    if (i < ns4) ((float4*)g_sout)[i] = z;
    if (i < nv4) ((float4*)g_vout)[i] = z;
}

// ---------------------------------------------------------------------------
// Node pre-GEMM: P = s @ W1[0:128] + b1 ; Q = s @ W1[128:256]
// ---------------------------------------------------------------------------
__global__ __launch_bounds__(NTHREADS, 1)
void node_pre_kernel(const float* __restrict__ s,
                     const float* __restrict__ W1,
                     const float* __restrict__ b1) {
    float* Xs = smem_f;                 // TE x XPITCH
    float* Wb = Xs + TE * XPITCH;       // 16 x 128
    int tid = threadIdx.x;
    int n0 = blockIdx.x * TE;
    int half = blockIdx.y;
    const float* W = W1 + (size_t)half * DS * DS;

    for (int idx = tid; idx < TE * 32; idx += NTHREADS) {
        int e = idx >> 5, k4 = idx & 31;
        int n = n0 + e;
        float4 v = make_float4(0.f, 0.f, 0.f, 0.f);
        if (n < NN) v = ((const float4*)(s + (size_t)n * DS))[k4];
        *(float4*)&Xs[e * XPITCH + k4 * 4] = v;
    }

    int c = tid & 15, r = tid >> 4;
    ull acc2[8][4];
#pragma unroll
    for (int i = 0; i < 8; ++i)
#pragma unroll
        for (int j = 0; j < 4; ++j) acc2[i][j] = 0ull;

    gemm_128(Xs, W, Wb, c, r, acc2);

    float bb[8];
    if (half == 0) {
#pragma unroll
        for (int j = 0; j < 8; ++j) bb[j] = __ldg(b1 + c * 8 + j);
    } else {
#pragma unroll
        for (int j = 0; j < 8; ++j) bb[j] = 0.f;
    }
    float* out = half ? g_Q : g_P;
#pragma unroll
    for (int i = 0; i < 8; ++i) {
        int n = n0 + r * 8 + i;
        if (n >= NN) continue;
        float2 a0 = unpack2(acc2[i][0]), a1 = unpack2(acc2[i][1]);
        float2 a2 = unpack2(acc2[i][2]), a3 = unpack2(acc2[i][3]);
        float4 o0 = make_float4(a0.x + bb[0], a0.y + bb[1], a1.x + bb[2], a1.y + bb[3]);
        float4 o1 = make_float4(a2.x + bb[4], a2.y + bb[5], a3.x + bb[6], a3.y + bb[7]);
        float4* dst = (float4*)(out + (size_t)n * DS + c * 8);
        dst[0] = o0;
        dst[1] = o1;
    }
}

// ---------------------------------------------------------------------------
// Edge kernel: per 128-edge tile
//   h1 = silu(EA@W1c + P[row] + Q[col])      (b1 folded into P)
//   msg = h1@W2 + b2       -> red.v4 into g_sout[row]
//   g  = silu(msg)@Wv + bv -> red.v4 g*unit into g_vout[row]
// Single Xs tile reused: EA -> h1 -> h2.
// ---------------------------------------------------------------------------
__global__ __launch_bounds__(NTHREADS, 1)
void edge_kernel(const int* __restrict__ ei,
                 const float* __restrict__ ea,
                 const float* __restrict__ evu,
                 const float* __restrict__ W1,
                 const float* __restrict__ W2,
                 const float* __restrict__ b2,
                 const float* __restrict__ Wv,
                 const float* __restrict__ bv) {
    float* Xs = smem_f;                      // TE x XPITCH
    float* Wb = Xs + TE * XPITCH;            // 16 x 128
    int* rows = (int*)(Wb + 16 * DS);        // TE
    int* cols = rows + TE;                   // TE
    float* uv = (float*)(cols + TE);         // TE x 3

    int tid = threadIdx.x;
    int e0 = blockIdx.x * TE;

    if (tid < TE) {
        rows[tid] = ei[e0 + tid];
        cols[tid] = ei[EE + e0 + tid];
    }
    for (int idx = tid; idx < TE * 3; idx += NTHREADS)
        uv[idx] = evu[(size_t)e0 * 3 + idx];
    for (int idx = tid; idx < TE * 32; idx += NTHREADS) {
        int e = idx >> 5, k4 = idx & 31;
        *(float4*)&Xs[e * XPITCH + k4 * 4] =
            ((const float4*)(ea + (size_t)(e0 + e) * DS))[k4];
    }
    // gemm's leading __syncthreads() publishes rows/cols/uv/Xs

    int c = tid & 15, r = tid >> 4;
    ull acc2[8][4];
#pragma unroll
    for (int i = 0; i < 8; ++i)
#pragma unroll
        for (int j = 0; j < 4; ++j) acc2[i][j] = 0ull;

    // GEMM1: EA @ W1c  (rows 256..383 of W1)
    gemm_128(Xs, W1 + (size_t)2 * DS * DS, Wb, c, r, acc2);

    // h1 = silu(acc + P[row] + Q[col])  -> overwrite Xs
    __syncthreads();  // all GEMM1 reads of Xs complete
#pragma unroll
    for (int i = 0; i < 8; ++i) {
        int e = r * 8 + i;
        const float4* pp = (const float4*)(g_P + (size_t)rows[e] * DS + c * 8);
        const float4* qp = (const float4*)(g_Q + (size_t)cols[e] * DS + c * 8);
        float4 p0 = pp[0], p1 = pp[1], q0 = qp[0], q1 = qp[1];
        float2 a0 = unpack2(acc2[i][0]), a1 = unpack2(acc2[i][1]);
        float2 a2 = unpack2(acc2[i][2]), a3 = unpack2(acc2[i][3]);
        float4 h0, h1v;
        h0.x = silu_f(a0.x + p0.x + q0.x);
        h0.y = silu_f(a0.y + p0.y + q0.y);
        h0.z = silu_f(a1.x + p0.z + q0.z);
        h0.w = silu_f(a1.y + p0.w + q0.w);
        h1v.x = silu_f(a2.x + p1.x + q1.x);
        h1v.y = silu_f(a2.y + p1.y + q1.y);
        h1v.z = silu_f(a3.x + p1.z + q1.z);
        h1v.w = silu_f(a3.y + p1.w + q1.w);
        *(float4*)&Xs[e * XPITCH + c * 8] = h0;
        *(float4*)&Xs[e * XPITCH + c * 8 + 4] = h1v;
    }

#pragma unroll
    for (int i = 0; i < 8; ++i)
#pragma unroll
        for (int j = 0; j < 4; ++j) acc2[i][j] = 0ull;

    // GEMM2: h1 @ W2
    gemm_128(Xs, W2, Wb, c, r, acc2);

    float bb[8];
#pragma unroll
    for (int j = 0; j < 8; ++j) bb[j] = __ldg(b2 + c * 8 + j);

    __syncthreads();  // all GEMM2 reads of Xs complete
#pragma unroll
    for (int i = 0; i < 8; ++i) {
        int e = r * 8 + i;
        int rw = rows[e];
        float2 a0 = unpack2(acc2[i][0]), a1 = unpack2(acc2[i][1]);
        float2 a2 = unpack2(acc2[i][2]), a3 = unpack2(acc2[i][3]);
        float m0 = a0.x + bb[0], m1 = a0.y + bb[1], m2 = a1.x + bb[2], m3 = a1.y + bb[3];
        float m4 = a2.x + bb[4], m5 = a2.y + bb[5], m6 = a3.x + bb[6], m7 = a3.y + bb[7];
        float* sdst = g_sout + (size_t)rw * DS + c * 8;
        red4(sdst, m0, m1, m2, m3);
        red4(sdst + 4, m4, m5, m6, m7);
        float4 h0 = make_float4(silu_f(m0), silu_f(m1), silu_f(m2), silu_f(m3));
        float4 h1v = make_float4(silu_f(m4), silu_f(m5), silu_f(m6), silu_f(m7));
        *(float4*)&Xs[e * XPITCH + c * 8] = h0;
        *(float4*)&Xs[e * XPITCH + c * 8 + 4] = h1v;
    }

    // GEMM3: h2 @ Wv (128x64). Thread map: c3 = tid&7 (4 j-pairs), r3 = tid>>3 (4 rows)
    int c3 = tid & 7, r3 = tid >> 3;
    ull acc3[4][4];
#pragma unroll
    for (int i = 0; i < 4; ++i)
#pragma unroll
        for (int j = 0; j < 4; ++j) acc3[i][j] = 0ull;

    for (int kc = 0; kc < DS; kc += 16) {
        __syncthreads();  // h2 writes visible (first iter); Wb free
        {
            int kk = tid >> 4, j4 = tid & 15;  // 256 threads -> 16x16 float4
            *(float4*)&Wb[kk * DV + j4 * 4] =
                __ldg((const float4*)(Wv + (size_t)(kc + kk) * DV) + j4);
        }
        __syncthreads();
#pragma unroll
        for (int kk4 = 0; kk4 < 4; ++kk4) {
            float4 xq[4];
#pragma unroll
            for (int i = 0; i < 4; ++i)
                xq[i] = *(const float4*)&Xs[(r3 * 4 + i) * XPITCH + kc + kk4 * 4];
#pragma unroll
            for (int t = 0; t < 4; ++t) {
                int kk = kk4 * 4 + t;
                const ulonglong2* wp = (const ulonglong2*)&Wb[kk * DV + c3 * 8];
                ulonglong2 wa = wp[0];
                ulonglong2 wbp = wp[1];
#pragma unroll
                for (int i = 0; i < 4; ++i) {
                    ull xs = splat2(((const float*)&xq[i])[t]);
                    ffma2(acc3[i][0], xs, wa.x);
                    ffma2(acc3[i][1], xs, wa.y);
                    ffma2(acc3[i][2], xs, wbp.x);
                    ffma2(acc3[i][3], xs, wbp.y);
                }
            }
        }
    }

    float bb3[8];
#pragma unroll
    for (int j = 0; j < 8; ++j) bb3[j] = __ldg(bv + c3 * 8 + j);
#pragma unroll
    for (int i = 0; i < 4; ++i) {
        int e = r3 * 4 + i;
        int rw = rows[e];
        float ux = uv[e * 3 + 0], uy = uv[e * 3 + 1], uz = uv[e * 3 + 2];
        float2 a0 = unpack2(acc3[i][0]), a1 = unpack2(acc3[i][1]);
        float2 a2 = unpack2(acc3[i][2]), a3 = unpack2(acc3[i][3]);
        float g[8] = {a0.x + bb3[0], a0.y + bb3[1], a1.x + bb3[2], a1.y + bb3[3],
                      a2.x + bb3[4], a2.y + bb3[5], a3.x + bb3[6], a3.y + bb3[7]};
        float vals[24];
#pragma unroll
        for (int j = 0; j < 8; ++j) {
            vals[j * 3 + 0] = g[j] * ux;
            vals[j * 3 + 1] = g[j] * uy;
            vals[j * 3 + 2] = g[j] * uz;
        }
        // 24 contiguous floats, 16B-aligned (rw*192 + c3*24 multiple of 4 floats)
        float* vd = g_vout + (size_t)rw * (DV * 3) + c3 * 24;
#pragma unroll
        for (int q = 0; q < 6; ++q)
            red4(vd + q * 4, vals[q * 4], vals[q * 4 + 1], vals[q * 4 + 2],
                 vals[q * 4 + 3]);
    }
}

// ---------------------------------------------------------------------------
// Node post: s_mid = s + silu(g_sout)@Ws + bs ; LayerNorm -> out_s
// ---------------------------------------------------------------------------
__global__ __launch_bounds__(NTHREADS, 1)
void node_post_kernel(const float* __restrict__ s,
                      const float* __restrict__ Ws,
                      const float* __restrict__ bs,
                      const float* __restrict__ gamma,
                      const float* __restrict__ beta,
                      float* __restrict__ out_s) {
    float* Xs = smem_f;                   // TE x XPITCH (silu(s_out))
    float* Hs = Xs + TE * XPITCH;         // TE x XPITCH (s_mid)
    float* Wb = Hs + TE * XPITCH;         // 16 x 128
    float* mu = Wb + 16 * DS;             // TE
    float* rs = mu + TE;                  // TE

    int tid = threadIdx.x;
    int n0 = blockIdx.x * TE;

    for (int idx = tid; idx < TE * 32; idx += NTHREADS) {
        int e = idx >> 5, k4 = idx & 31;
        int n = n0 + e;
        float4 v = make_float4(0.f, 0.f, 0.f, 0.f);
        if (n < NN) {
            v = ((const float4*)(g_sout + (size_t)n * DS))[k4];
            v.x = silu_f(v.x); v.y = silu_f(v.y);
            v.z = silu_f(v.z); v.w = silu_f(v.w);
        }
        *(float4*)&Xs[e * XPITCH + k4 * 4] = v;
    }

    int c = tid & 15, r = tid >> 4;
    ull acc2[8][4];
#pragma unroll
    for (int i = 0; i < 8; ++i)
#pragma unroll
        for (int j = 0; j < 4; ++j) acc2[i][j] = 0ull;

    gemm_128(Xs, Ws, Wb, c, r, acc2);

    float bb[8];
#pragma unroll
    for (int j = 0; j < 8; ++j) bb[j] = __ldg(bs + c * 8 + j);
#pragma unroll
    for (int i = 0; i < 8; ++i) {
        int n = n0 + r * 8 + i;
        float4 s0 = make_float4(0.f, 0.f, 0.f, 0.f);
        float4 s1 = make_float4(0.f, 0.f, 0.f, 0.f);
        if (n < NN) {
            const float4* sp = (const float4*)(s + (size_t)n * DS + c * 8);
            s0 = sp[0];
            s1 = sp[1];
        }
        float2 a0 = unpack2(acc2[i][0]), a1 = unpack2(acc2[i][1]);
        float2 a2 = unpack2(acc2[i][2]), a3 = unpack2(acc2[i][3]);
        float* hr = &Hs[(r * 8 + i) * XPITCH + c * 8];
        hr[0] = s0.x + a0.x + bb[0];
        hr[1] = s0.y + a0.y + bb[1];
        hr[2] = s0.z + a1.x + bb[2];
        hr[3] = s0.w + a1.y + bb[3];
        hr[4] = s1.x + a2.x + bb[4];
        hr[5] = s1.y + a2.y + bb[5];
        hr[6] = s1.z + a3.x + bb[6];
        hr[7] = s1.w + a3.y + bb[7];
    }
    __syncthreads();

    if (tid < TE) {
        float sum = 0.f, sq = 0.f;
#pragma unroll 8
        for (int k = 0; k < DS; ++k) {
            float x = Hs[tid * XPITCH + k];
            sum += x;
            sq += x * x;
        }
        float m = sum * (1.0f / DS);
        float var = sq * (1.0f / DS) - m * m;
        mu[tid] = m;
        rs[tid] = rsqrtf(var + 1e-5f);
    }
    __syncthreads();

    for (int idx = tid; idx < TE * 32; idx += NTHREADS) {
        int e = idx >> 5, j4 = idx & 31;
        int n = n0 + e;
        if (n >= NN) continue;
        float4 x = *(const float4*)&Hs[e * XPITCH + j4 * 4];
        float4 g = __ldg((const float4*)gamma + j4);
        float4 b = __ldg((const float4*)beta + j4);
        float m = mu[e], iv = rs[e];
        float4 o;
        o.x = (x.x - m) * iv * g.x + b.x;
        o.y = (x.y - m) * iv * g.y + b.y;
        o.z = (x.z - m) * iv * g.z + b.z;
        o.w = (x.w - m) * iv * g.w + b.w;
        ((float4*)(out_s + (size_t)n * DS))[j4] = o;
    }
}

// ---------------------------------------------------------------------------
// v_new = v + v_out
// ---------------------------------------------------------------------------
__global__ void vadd_kernel(const float* __restrict__ v, float* __restrict__ out_v) {
    int i = blockIdx.x * blockDim.x + threadIdx.x;
    constexpr int nv4 = NN * DV * 3 / 4;
    if (i < nv4) {
        float4 a = ((const float4*)v)[i];
        float4 b = ((const float4*)g_vout)[i];
        a.x += b.x; a.y += b.y; a.z += b.z; a.w += b.w;
        ((float4*)out_v)[i] = a;
    }
}

// ---------------------------------------------------------------------------
extern "C" void kernel_launch(void* const* d_in, const int* in_sizes, int n_in,
                              void* d_out, int out_size) {
    const float* s     = (const float*)d_in[0];
    const float* v     = (const float*)d_in[1];
    const int*   ei    = (const int*)d_in[2];
    const float* ea    = (const float*)d_in[3];
    const float* evu   = (const float*)d_in[4];
    const float* W1    = (const float*)d_in[5];
    const float* b1    = (const float*)d_in[6];
    const float* W2    = (const float*)d_in[7];
    const float* b2    = (const float*)d_in[8];
    const float* Ws    = (const float*)d_in[9];
    const float* bs    = (const float*)d_in[10];
    const float* Wv    = (const float*)d_in[11];
    const float* bv    = (const float*)d_in[12];
    const float* gamma = (const float*)d_in[13];
    const float* beta  = (const float*)d_in[14];
    float* out = (float*)d_out;

    const int SMEM_PRE  = (TE * XPITCH + 16 * DS) * 4;
    const int SMEM_EDGE = (TE * XPITCH + 16 * DS) * 4 + 2 * TE * 4 + TE * 3 * 4;
    const int SMEM_POST = (2 * TE * XPITCH + 16 * DS) * 4 + 2 * TE * 4;

    cudaFuncSetAttribute(node_pre_kernel,
                         cudaFuncAttributeMaxDynamicSharedMemorySize, SMEM_PRE);
    cudaFuncSetAttribute(edge_kernel,
                         cudaFuncAttributeMaxDynamicSharedMemorySize, SMEM_EDGE);
    cudaFuncSetAttribute(node_post_kernel,
                         cudaFuncAttributeMaxDynamicSharedMemorySize, SMEM_POST);

    zero_kernel<<<(NN * DV * 3 / 4 + 255) / 256, 256>>>();

    dim3 gpre((NN + TE - 1) / TE, 2);
    node_pre_kernel<<<gpre, NTHREADS, SMEM_PRE>>>(s, W1, b1);

    edge_kernel<<<EE / TE, NTHREADS, SMEM_EDGE>>>(ei, ea, evu, W1, W2, b2, Wv, bv);

    node_post_kernel<<<(NN + TE - 1) / TE, NTHREADS, SMEM_POST>>>(s, Ws, bs, gamma,
                                                                  beta, out);

    vadd_kernel<<<(NN * DV * 3 / 4 + 255) / 256, 256>>>(v, out + (size_t)NN * DS);
}